// round 4
// baseline (speedup 1.0000x reference)
#include <cuda_runtime.h>
#include <cuda_bf16.h>

#define N_NODES 100000
#define HDIM 128
#define KNBR 16

// Per-node attention scores (scratch; device global => no allocation).
__device__ float g_score[N_NODES];

__device__ __forceinline__ unsigned pack_bf162(float lo, float hi) {
    __nv_bfloat162 h = __floats2bfloat162_rn(lo, hi);
    return *reinterpret_cast<unsigned*>(&h);
}

// ---------------------------------------------------------------------------
// Kernel 1: score[n] = ua . leaky_relu(Wa @ e_n + b)
// Warp computes 16 nodes via mma.sync m16n8k16 bf16 (fp32 accum).
// h = e @ Wa^T  => B[k][j] = Wa[j][k]; Wa rows are k-contiguous, so B "col"
// fragments load directly from Wa with a float2->bf16x2 convert.
// ---------------------------------------------------------------------------
__global__ __launch_bounds__(128) void score_kernel(
    const float* __restrict__ e,
    const float* __restrict__ Wa,
    const float* __restrict__ bias,
    const float* __restrict__ ua)
{
    const int lane = threadIdx.x & 31;
    const int warp = threadIdx.x >> 5;
    const int row0 = blockIdx.x * 64 + warp * 16;
    if (row0 >= N_NODES) return;

    float acc[64];
#pragma unroll
    for (int i = 0; i < 64; i++) acc[i] = 0.f;

    const int rA0 = row0 + (lane >> 2);
    const int rA1 = rA0 + 8;
    const int rA0c = rA0 < N_NODES ? rA0 : N_NODES - 1;
    const int rA1c = rA1 < N_NODES ? rA1 : N_NODES - 1;
    const int kc = (lane & 3) * 2;

    const float* eptr0 = e + rA0c * HDIM + kc;
    const float* eptr1 = e + rA1c * HDIM + kc;
    const float* wptr  = Wa + (lane >> 2) * HDIM + kc;

#pragma unroll
    for (int k0 = 0; k0 < 8; k0++) {
        const int kb = k0 * 16;
        float2 fa0 = *(const float2*)(eptr0 + kb);
        float2 fa1 = *(const float2*)(eptr1 + kb);
        float2 fa2 = *(const float2*)(eptr0 + kb + 8);
        float2 fa3 = *(const float2*)(eptr1 + kb + 8);
        unsigned a0 = pack_bf162(fa0.x, fa0.y);
        unsigned a1 = pack_bf162(fa1.x, fa1.y);
        unsigned a2 = pack_bf162(fa2.x, fa2.y);
        unsigned a3 = pack_bf162(fa3.x, fa3.y);

#pragma unroll
        for (int nt = 0; nt < 16; nt++) {
            float2 fb0 = *(const float2*)(wptr + nt * 8 * HDIM + kb);
            float2 fb1 = *(const float2*)(wptr + nt * 8 * HDIM + kb + 8);
            unsigned b0 = pack_bf162(fb0.x, fb0.y);
            unsigned b1 = pack_bf162(fb1.x, fb1.y);
            asm volatile(
                "mma.sync.aligned.m16n8k16.row.col.f32.bf16.bf16.f32 "
                "{%0,%1,%2,%3}, {%4,%5,%6,%7}, {%8,%9}, {%0,%1,%2,%3};\n"
                : "+f"(acc[nt*4+0]), "+f"(acc[nt*4+1]),
                  "+f"(acc[nt*4+2]), "+f"(acc[nt*4+3])
                : "r"(a0), "r"(a1), "r"(a2), "r"(a3), "r"(b0), "r"(b1));
        }
    }

    // Epilogue: + bias, leaky(0.1), dot with ua, reduce per node.
    // acc[4nt+0]=(r,c0) acc[4nt+1]=(r,c0+1) acc[4nt+2]=(r+8,c0) acc[4nt+3]=(r+8,c0+1)
    float ps0 = 0.f, ps1 = 0.f;
#pragma unroll
    for (int nt = 0; nt < 16; nt++) {
        const int c0 = nt * 8 + kc;
        const float b0v = bias[c0], b1v = bias[c0 + 1];
        const float u0 = ua[c0], u1 = ua[c0 + 1];
        float h;
        h = acc[nt*4+0] + b0v; h = h > 0.f ? h : 0.1f * h; ps0 = fmaf(u0, h, ps0);
        h = acc[nt*4+1] + b1v; h = h > 0.f ? h : 0.1f * h; ps0 = fmaf(u1, h, ps0);
        h = acc[nt*4+2] + b0v; h = h > 0.f ? h : 0.1f * h; ps1 = fmaf(u0, h, ps1);
        h = acc[nt*4+3] + b1v; h = h > 0.f ? h : 0.1f * h; ps1 = fmaf(u1, h, ps1);
    }
    // Reduce across the 4 lanes of each row-group (lane&3 varies).
    ps0 += __shfl_xor_sync(0xffffffffu, ps0, 1);
    ps0 += __shfl_xor_sync(0xffffffffu, ps0, 2);
    ps1 += __shfl_xor_sync(0xffffffffu, ps1, 1);
    ps1 += __shfl_xor_sync(0xffffffffu, ps1, 2);
    if ((lane & 3) == 0) {
        if (rA0 < N_NODES) g_score[rA0] = ps0;
        if (rA1 < N_NODES) g_score[rA1] = ps1;
    }
}

// ---------------------------------------------------------------------------
// Kernel 2: softmax over K neighbor scores, weighted aggregate, residual add.
// One warp per node; 16 fully-coalesced 512B row gathers (L2-resident e).
// neighbors is int32 on the wire (JAX canonicalizes int64 -> int32).
// ---------------------------------------------------------------------------
__global__ __launch_bounds__(256) void agg_kernel(
    const float* __restrict__ e,
    const int* __restrict__ nbr,
    float* __restrict__ out)
{
    __shared__ float wsh[8][KNBR];
    __shared__ int   ish[8][KNBR];

    const int warp = threadIdx.x >> 5;
    const int lane = threadIdx.x & 31;
    const int node = blockIdx.x * 8 + warp;
    if (node >= N_NODES) return;

    float s = -1e30f;
    int nb = 0;
    if (lane < KNBR) {
        nb = nbr[node * KNBR + lane];
        // Safety clamp: if dtype assumption is wrong we get a wrong answer,
        // not a crash (diagnostic property, ~zero cost under L2 latency).
        nb = (nb < 0) ? 0 : (nb >= N_NODES ? N_NODES - 1 : nb);
        s = g_score[nb];
    }
    float m = s;
#pragma unroll
    for (int off = 16; off >= 1; off >>= 1)
        m = fmaxf(m, __shfl_xor_sync(0xffffffffu, m, off));
    float w = (lane < KNBR) ? __expf(s - m) : 0.f;
    float sum = w;
#pragma unroll
    for (int off = 16; off >= 1; off >>= 1)
        sum += __shfl_xor_sync(0xffffffffu, sum, off);
    if (lane < KNBR) {
        wsh[warp][lane] = w / sum;
        ish[warp][lane] = nb;
    }
    __syncwarp();

    const int c = lane * 4;
    float4 acc = *(const float4*)(e + (size_t)node * HDIM + c);
#pragma unroll
    for (int k = 0; k < KNBR; k++) {
        const int r = ish[warp][k];
        const float wk = wsh[warp][k];
        float4 v = *(const float4*)(e + (size_t)r * HDIM + c);
        acc.x = fmaf(wk, v.x, acc.x);
        acc.y = fmaf(wk, v.y, acc.y);
        acc.z = fmaf(wk, v.z, acc.z);
        acc.w = fmaf(wk, v.w, acc.w);
    }
    *(float4*)(out + (size_t)node * HDIM + c) = acc;
}

extern "C" void kernel_launch(void* const* d_in, const int* in_sizes, int n_in,
                              void* d_out, int out_size)
{
    const float* e    = (const float*)d_in[0];
    const float* Wa   = (const float*)d_in[1];
    const float* bias = (const float*)d_in[2];
    const float* ua   = (const float*)d_in[3];
    const int*   nbr  = (const int*)d_in[4];
    float*       out  = (float*)d_out;

    score_kernel<<<(N_NODES + 63) / 64, 128>>>(e, Wa, bias, ua);
    agg_kernel<<<(N_NODES + 7) / 8, 256>>>(e, nbr, out);
}

// round 16
// speedup vs baseline: 1.2914x; 1.2914x over previous
#include <cuda_runtime.h>
#include <cuda_bf16.h>

#define N_NODES 100000
#define HDIM 128
#define KNBR 16
#define WA_STRIDE 68  // 4B words per smem row: 68 mod 32 == 4 -> conflict-free frags

// Scratch (device globals => no allocation).
__device__ float g_score[N_NODES];
__device__ __nv_bfloat16 g_ebf[(size_t)N_NODES * HDIM];  // bf16 copy of e for gathers

__device__ __forceinline__ unsigned pack_bf162(float lo, float hi) {
    __nv_bfloat162 h = __floats2bfloat162_rn(lo, hi);
    return *reinterpret_cast<unsigned*>(&h);
}

// ---------------------------------------------------------------------------
// Kernel 0: e (fp32) -> g_ebf (bf16), fully coalesced.
// ---------------------------------------------------------------------------
__global__ __launch_bounds__(256) void cvt_kernel(const float* __restrict__ e)
{
    const int i = blockIdx.x * 256 + threadIdx.x;   // float4 index
    if (i < N_NODES * HDIM / 4) {
        float4 f = ((const float4*)e)[i];
        uint2 o;
        o.x = pack_bf162(f.x, f.y);
        o.y = pack_bf162(f.z, f.w);
        ((uint2*)g_ebf)[i] = o;
    }
}

// ---------------------------------------------------------------------------
// Kernel 1: score[n] = ua . leaky_relu(Wa @ e_n + b)
// Warp computes 16 nodes via mma.sync m16n8k16 bf16 (fp32 accum).
// Wa is staged once per CTA into smem as bf16x2 words with row stride 68
// (68 mod 32 == 4), so each fragment LDS.32 hits banks 4q+r+8k0 mod 32 — a
// permutation -> conflict-free. This replaces the R4 B-path whose LDG.64s
// spanned 8 rows (nL=8 wavefronts each) and bound the kernel at ~43 us.
// ---------------------------------------------------------------------------
__global__ __launch_bounds__(128) void score_kernel(
    const float* __restrict__ e,
    const float* __restrict__ Wa,
    const float* __restrict__ bias,
    const float* __restrict__ ua)
{
    __shared__ unsigned wa_sh[128 * WA_STRIDE];  // 34816 B

    const int tid  = threadIdx.x;
    const int lane = tid & 31;
    const int warp = tid >> 5;

    // Stage Wa -> smem bf16x2 (coalesced LDG.64 + F2FP + STS.32).
#pragma unroll 8
    for (int i = 0; i < 64; i++) {
        const int idx = i * 128 + tid;       // word index 0..8191
        const int row = idx >> 6;            // 64 words per 128-col row
        const int w   = idx & 63;
        float2 f = *(const float2*)(Wa + row * HDIM + w * 2);
        wa_sh[row * WA_STRIDE + w] = pack_bf162(f.x, f.y);
    }
    __syncthreads();

    const int row0 = blockIdx.x * 64 + warp * 16;
    if (row0 >= N_NODES) return;

    float acc[64];
#pragma unroll
    for (int i = 0; i < 64; i++) acc[i] = 0.f;

    const int q  = lane >> 2;      // row-in-fragment
    const int r  = lane & 3;       // k-pair slot
    const int kc = r * 2;

    const int rA0 = row0 + q;
    const int rA1 = rA0 + 8;
    const int rA0c = rA0 < N_NODES ? rA0 : N_NODES - 1;
    const int rA1c = rA1 < N_NODES ? rA1 : N_NODES - 1;

    const float* eptr0 = e + rA0c * HDIM + kc;
    const float* eptr1 = e + rA1c * HDIM + kc;
    const unsigned* bptr = wa_sh + q * WA_STRIDE + r;  // [q][r] base

#pragma unroll
    for (int k0 = 0; k0 < 8; k0++) {
        const int kb = k0 * 16;
        float2 fa0 = *(const float2*)(eptr0 + kb);
        float2 fa1 = *(const float2*)(eptr1 + kb);
        float2 fa2 = *(const float2*)(eptr0 + kb + 8);
        float2 fa3 = *(const float2*)(eptr1 + kb + 8);
        unsigned a0 = pack_bf162(fa0.x, fa0.y);
        unsigned a1 = pack_bf162(fa1.x, fa1.y);
        unsigned a2 = pack_bf162(fa2.x, fa2.y);
        unsigned a3 = pack_bf162(fa3.x, fa3.y);

        const unsigned* bk = bptr + k0 * 8;
#pragma unroll
        for (int nt = 0; nt < 16; nt++) {
            // [nt*8 + q][k0*8 + r] and +4 : identical values to the proven
            // R4 global-memory fragment mapping.
            unsigned b0 = bk[nt * 8 * WA_STRIDE];
            unsigned b1 = bk[nt * 8 * WA_STRIDE + 4];
            asm volatile(
                "mma.sync.aligned.m16n8k16.row.col.f32.bf16.bf16.f32 "
                "{%0,%1,%2,%3}, {%4,%5,%6,%7}, {%8,%9}, {%0,%1,%2,%3};\n"
                : "+f"(acc[nt*4+0]), "+f"(acc[nt*4+1]),
                  "+f"(acc[nt*4+2]), "+f"(acc[nt*4+3])
                : "r"(a0), "r"(a1), "r"(a2), "r"(a3), "r"(b0), "r"(b1));
        }
    }

    // Epilogue: + bias, leaky(0.1), dot with ua, reduce per node.
    float ps0 = 0.f, ps1 = 0.f;
#pragma unroll
    for (int nt = 0; nt < 16; nt++) {
        const int c0 = nt * 8 + kc;
        const float b0v = bias[c0], b1v = bias[c0 + 1];
        const float u0 = ua[c0], u1 = ua[c0 + 1];
        float h;
        h = acc[nt*4+0] + b0v; h = h > 0.f ? h : 0.1f * h; ps0 = fmaf(u0, h, ps0);
        h = acc[nt*4+1] + b1v; h = h > 0.f ? h : 0.1f * h; ps0 = fmaf(u1, h, ps0);
        h = acc[nt*4+2] + b0v; h = h > 0.f ? h : 0.1f * h; ps1 = fmaf(u0, h, ps1);
        h = acc[nt*4+3] + b1v; h = h > 0.f ? h : 0.1f * h; ps1 = fmaf(u1, h, ps1);
    }
    ps0 += __shfl_xor_sync(0xffffffffu, ps0, 1);
    ps0 += __shfl_xor_sync(0xffffffffu, ps0, 2);
    ps1 += __shfl_xor_sync(0xffffffffu, ps1, 1);
    ps1 += __shfl_xor_sync(0xffffffffu, ps1, 2);
    if (r == 0) {
        if (rA0 < N_NODES) g_score[rA0] = ps0;
        if (rA1 < N_NODES) g_score[rA1] = ps1;
    }
}

// ---------------------------------------------------------------------------
// Kernel 2: softmax over K neighbor scores, weighted aggregate, residual add.
// One warp per node. Gathers neighbor rows from the bf16 staged copy
// (256B/row instead of 512B -> halves the dominant L2 gather traffic).
// Residual + accumulation stay fp32.
// ---------------------------------------------------------------------------
__global__ __launch_bounds__(256) void agg_kernel(
    const float* __restrict__ e,
    const int* __restrict__ nbr,
    float* __restrict__ out)
{
    __shared__ float wsh[8][KNBR];
    __shared__ int   ish[8][KNBR];

    const int warp = threadIdx.x >> 5;
    const int lane = threadIdx.x & 31;
    const int node = blockIdx.x * 8 + warp;
    if (node >= N_NODES) return;

    float s = -1e30f;
    int nb = 0;
    if (lane < KNBR) {
        nb = nbr[node * KNBR + lane];
        nb = (nb < 0) ? 0 : (nb >= N_NODES ? N_NODES - 1 : nb);
        s = g_score[nb];
    }
    float m = s;
#pragma unroll
    for (int off = 16; off >= 1; off >>= 1)
        m = fmaxf(m, __shfl_xor_sync(0xffffffffu, m, off));
    float w = (lane < KNBR) ? __expf(s - m) : 0.f;
    float sum = w;
#pragma unroll
    for (int off = 16; off >= 1; off >>= 1)
        sum += __shfl_xor_sync(0xffffffffu, sum, off);
    if (lane < KNBR) {
        wsh[warp][lane] = w / sum;
        ish[warp][lane] = nb;
    }
    __syncwarp();

    const int c = lane * 4;  // this lane's 4 feature columns
    float4 acc = *(const float4*)(e + (size_t)node * HDIM + c);
#pragma unroll
    for (int k = 0; k < KNBR; k++) {
        const int r = ish[warp][k];
        const float wk = wsh[warp][k];
        uint2 v = *(const uint2*)(g_ebf + (size_t)r * HDIM + c);  // 4 bf16, 8B
        float2 p0 = __bfloat1622float2(*reinterpret_cast<__nv_bfloat162*>(&v.x));
        float2 p1 = __bfloat1622float2(*reinterpret_cast<__nv_bfloat162*>(&v.y));
        acc.x = fmaf(wk, p0.x, acc.x);
        acc.y = fmaf(wk, p0.y, acc.y);
        acc.z = fmaf(wk, p1.x, acc.z);
        acc.w = fmaf(wk, p1.y, acc.w);
    }
    *(float4*)(out + (size_t)node * HDIM + c) = acc;
}

extern "C" void kernel_launch(void* const* d_in, const int* in_sizes, int n_in,
                              void* d_out, int out_size)
{
    const float* e    = (const float*)d_in[0];
    const float* Wa   = (const float*)d_in[1];
    const float* bias = (const float*)d_in[2];
    const float* ua   = (const float*)d_in[3];
    const int*   nbr  = (const int*)d_in[4];
    float*       out  = (float*)d_out;

    cvt_kernel<<<(N_NODES * HDIM / 4 + 255) / 256, 256>>>(e);
    score_kernel<<<(N_NODES + 63) / 64, 128>>>(e, Wa, bias, ua);
    agg_kernel<<<(N_NODES + 7) / 8, 256>>>(e, nbr, out);
}